// round 14
// baseline (speedup 1.0000x reference)
#include <cuda_runtime.h>
#include <cuda_bf16.h>

// model_6408091205990: 1.23M independent tiny GRUs (T=10, I=1, H=5) + FC(5->3).
// Round-12: exact R3 math (best 57.8us, rel_err 2.45e-6).  Single change:
// __launch_bounds__(128, 3) -> ~168-reg budget so the ENTIRE weight set
// (~134 live values) stays register-resident; the ~25 per-step L1 weight
// reloads (lat ~39cyc, sitting inside the matvec dependency chains) vanish.
// Discriminates reload-latency-bound (predict 48-53us) vs intrinsic
// fma<->MUFU overlap floor (predict neutral; then R3 is final).

#define NB 4096
#define NT 10
#define NS 301
#define NH 5
#define NO 3
#define NSEQ (NB * NS)
#define THREADS 128

typedef unsigned long long ull;

__device__ __forceinline__ ull pack2(float lo, float hi) {
    ull r; asm("mov.b64 %0, {%1, %2};" : "=l"(r) : "f"(lo), "f"(hi)); return r;
}
__device__ __forceinline__ void unpack2(ull v, float& lo, float& hi) {
    asm("mov.b64 {%0, %1}, %2;" : "=f"(lo), "=f"(hi) : "l"(v));
}
__device__ __forceinline__ ull fma2(ull a, ull b, ull c) {
    ull d; asm("fma.rn.f32x2 %0, %1, %2, %3;" : "=l"(d) : "l"(a), "l"(b), "l"(c));
    return d;
}
__device__ __forceinline__ float tanh_mufu(float x) {
    float y; asm("tanh.approx.f32 %0, %1;" : "=f"(y) : "f"(x)); return y;
}

__global__ __launch_bounds__(THREADS, 3)
void gru_fused_kernel(const float* __restrict__ x,
                      const float* __restrict__ w_ih,
                      const float* __restrict__ w_hh,
                      const float* __restrict__ b_ih,
                      const float* __restrict__ b_hh,
                      const float* __restrict__ fc_w,
                      const float* __restrict__ fc_b,
                      float* __restrict__ out)
{
    const int n = blockIdx.x * THREADS + threadIdx.x;
    if (n >= NSEQ) return;
    const int b = n / NS;
    const int s = n - b * NS;

    // ---- weight prep (uniform broadcast loads; 0.5 folded into r/z rows) ----
    ull wrz_x[NH];        // (0.5*w_ih[r][j], 0.5*w_ih[z][j])
    ull brz2[NH];         // 0.5*(b_ih+b_hh) for (r, z)
    ull wrz_h[NH][NH];    // [j][k] = (0.5*w_hh[r,j,k], 0.5*w_hh[z,j,k])
    ull wn_h2[2][NH];     // [p][k] = (w_hh[n,2p,k], w_hh[n,2p+1,k])
    float wn_h4[NH];
    ull bn2[2];
    float bn4;
    ull win2[2], bin2[2];
    float win4, bin4;

    #pragma unroll
    for (int j = 0; j < NH; j++) {
        wrz_x[j] = pack2(0.5f * __ldg(&w_ih[j]), 0.5f * __ldg(&w_ih[NH + j]));
        brz2[j]  = pack2(0.5f * (__ldg(&b_ih[j]) + __ldg(&b_hh[j])),
                         0.5f * (__ldg(&b_ih[NH + j]) + __ldg(&b_hh[NH + j])));
        #pragma unroll
        for (int k = 0; k < NH; k++)
            wrz_h[j][k] = pack2(0.5f * __ldg(&w_hh[j * NH + k]),
                                0.5f * __ldg(&w_hh[(NH + j) * NH + k]));
    }
    #pragma unroll
    for (int p = 0; p < 2; p++) {
        bn2[p]  = pack2(__ldg(&b_hh[2 * NH + 2 * p]), __ldg(&b_hh[2 * NH + 2 * p + 1]));
        win2[p] = pack2(__ldg(&w_ih[2 * NH + 2 * p]), __ldg(&w_ih[2 * NH + 2 * p + 1]));
        bin2[p] = pack2(__ldg(&b_ih[2 * NH + 2 * p]), __ldg(&b_ih[2 * NH + 2 * p + 1]));
        #pragma unroll
        for (int k = 0; k < NH; k++)
            wn_h2[p][k] = pack2(__ldg(&w_hh[(2 * NH + 2 * p) * NH + k]),
                                __ldg(&w_hh[(2 * NH + 2 * p + 1) * NH + k]));
    }
    bn4  = __ldg(&b_hh[2 * NH + 4]);
    win4 = __ldg(&w_ih[2 * NH + 4]);
    bin4 = __ldg(&b_ih[2 * NH + 4]);
    #pragma unroll
    for (int k = 0; k < NH; k++) wn_h4[k] = __ldg(&w_hh[(2 * NH + 4) * NH + k]);

    const ull NEG1_2 = pack2(-1.0f, -1.0f);

    // ---- GRU recurrence, fully unrolled -------------------------------------
    float h[NH] = {0.f, 0.f, 0.f, 0.f, 0.f};
    ull h01 = pack2(0.f, 0.f), h23 = h01;
    const float* xp = x + (size_t)b * (NT * NS) + s;

    #pragma unroll
    for (int t = 0; t < NT; t++) {
        const float xv = __ldg(xp + t * NS);
        const ull xv2 = pack2(xv, xv);

        // r/z pre-activations (0.5-scaled): x part
        ull arz[NH];
        #pragma unroll
        for (int j = 0; j < NH; j++) arz[j] = fma2(xv2, wrz_x[j], brz2[j]);

        // n-gate hidden part
        ull an2[2] = {bn2[0], bn2[1]};
        float ah4 = bn4;

        if (t > 0) {  // h == 0 at t == 0: skip the entire h-matvec
            ull hb[NH];
            #pragma unroll
            for (int k = 0; k < NH; k++) hb[k] = pack2(h[k], h[k]);
            #pragma unroll
            for (int k = 0; k < NH; k++) {
                #pragma unroll
                for (int j = 0; j < NH; j++)
                    arz[j] = fma2(wrz_h[j][k], hb[k], arz[j]);
                an2[0] = fma2(wn_h2[0][k], hb[k], an2[0]);
                an2[1] = fma2(wn_h2[1][k], hb[k], an2[1]);
                ah4 = fmaf(wn_h4[k], h[k], ah4);
            }
        }
        float ah[NH];
        unpack2(an2[0], ah[0], ah[1]);
        unpack2(an2[1], ah[2], ah[3]);
        ah[4] = ah4;

        // n-gate x-projection, packed across j pairs
        float ai[NH];
        {
            ull ai01 = fma2(xv2, win2[0], bin2[0]);
            ull ai23 = fma2(xv2, win2[1], bin2[1]);
            unpack2(ai01, ai[0], ai[1]);
            unpack2(ai23, ai[2], ai[3]);
            ai[4] = fmaf(xv, win4, bin4);
        }

        // gate epilogue: sigmoid via 0.5*tanh(0.5x)+0.5, r/z pair-packed
        const ull HALF2 = pack2(0.5f, 0.5f);
        float z[NH], nn[NH];
        #pragma unroll
        for (int j = 0; j < NH; j++) {
            float ar, az;
            unpack2(arz[j], ar, az);
            ull t2 = pack2(tanh_mufu(ar), tanh_mufu(az));
            ull rz = fma2(HALF2, t2, HALF2);
            float r;
            unpack2(rz, r, z[j]);
            nn[j] = tanh_mufu(fmaf(r, ah[j], ai[j]));
        }

        // h update (1-z)*n + z*h = z*(h-n) + n, j-pair packed
        {
            ull nn01 = pack2(nn[0], nn[1]);
            ull nn23 = pack2(nn[2], nn[3]);
            ull z01  = pack2(z[0], z[1]);
            ull z23  = pack2(z[2], z[3]);
            h01 = fma2(z01, fma2(nn01, NEG1_2, h01), nn01);
            h23 = fma2(z23, fma2(nn23, NEG1_2, h23), nn23);
            h[4] = fmaf(z[4], h[4] - nn[4], nn[4]);
            unpack2(h01, h[0], h[1]);
            unpack2(h23, h[2], h[3]);
        }
    }

    // ---- FC(5 -> 3), strided write out[b][o][s] -----------------------------
    #pragma unroll
    for (int o = 0; o < NO; o++) {
        float y = __ldg(&fc_b[o]);
        #pragma unroll
        for (int k = 0; k < NH; k++) y = fmaf(__ldg(&fc_w[o * NH + k]), h[k], y);
        out[((size_t)b * NO + o) * NS + s] = y;
    }
}

extern "C" void kernel_launch(void* const* d_in, const int* in_sizes, int n_in,
                              void* d_out, int out_size)
{
    const float* x    = (const float*)d_in[0];
    const float* w_ih = (const float*)d_in[1];
    const float* w_hh = (const float*)d_in[2];
    const float* b_ih = (const float*)d_in[3];
    const float* b_hh = (const float*)d_in[4];
    const float* fc_w = (const float*)d_in[5];
    const float* fc_b = (const float*)d_in[6];
    float* out = (float*)d_out;

    const int grid = (NSEQ + THREADS - 1) / THREADS;
    gru_fused_kernel<<<grid, THREADS>>>(x, w_ih, w_hh, b_ih, b_hh, fc_w, fc_b, out);
}

// round 17
// speedup vs baseline: 1.1788x; 1.1788x over previous
#include <cuda_runtime.h>
#include <cuda_bf16.h>
#include <cstdint>

// model_6408091205990: 1.23M independent tiny GRUs (T=10, I=1, H=5) + FC(5->3).
// Round-14: tcgen05 unavailable (harness targets compute_103 PTX).  Attack the
// validated fma floor instead: FFMA2 runs rt3 because all 3 operands are RF
// pairs (3 even + 3 odd banks).  Weights are warp-uniform -> move them to
// __constant__ memory so ptxas emits LDCU -> UR and FFMA2 takes a UR operand
// (2 RF pairs -> rt2).  Weight packing done once per launch by a prep kernel +
// cudaMemcpyToSymbolAsync (async D2D, allocation-free, graph-capturable).
// Math identical to R3 (57.8us, rel_err 2.45e-6); fma/step 177 -> ~130 if the
// UR promotion lands.

#define NB 4096
#define NT 10
#define NS 301
#define NH 5
#define NO 3
#define NSEQ (NB * NS)
#define THREADS 128

typedef unsigned long long ull;

__device__ __forceinline__ ull pack2(float lo, float hi) {
    ull r; asm("mov.b64 %0, {%1, %2};" : "=l"(r) : "f"(lo), "f"(hi)); return r;
}
__device__ __forceinline__ void unpack2(ull v, float& lo, float& hi) {
    asm("mov.b64 {%0, %1}, %2;" : "=f"(lo), "=f"(hi) : "l"(v));
}
__device__ __forceinline__ ull fma2(ull a, ull b, ull c) {
    ull d; asm("fma.rn.f32x2 %0, %1, %2, %3;" : "=l"(d) : "l"(a), "l"(b), "l"(c));
    return d;
}
__device__ __forceinline__ float tanh_mufu(float x) {
    float y; asm("tanh.approx.f32 %0, %1;" : "=f"(y) : "f"(x)); return y;
}

// ---- packed weights, built on device once per launch ------------------------
struct CW {
    ull wrz_x[NH];        // (0.5*w_ih[r][j], 0.5*w_ih[z][j])
    ull brz2[NH];         // 0.5*(b_ih+b_hh) for (r, z)
    ull wrz_h[NH][NH];    // [j][k] = (0.5*w_hh[r,j,k], 0.5*w_hh[z,j,k])
    ull wn_h2[2][NH];     // [p][k] = (w_hh[n,2p,k], w_hh[n,2p+1,k])
    ull bn2[2];
    ull win2[2], bin2[2];
    float wn_h4[NH];
    float bn4, win4, bin4;
    float fcw[NO][NH];
    float fcb[NO];
};
__constant__ CW cW;
__device__ CW gScratch;

__global__ void prep_kernel(const float* __restrict__ w_ih,
                            const float* __restrict__ w_hh,
                            const float* __restrict__ b_ih,
                            const float* __restrict__ b_hh,
                            const float* __restrict__ fc_w,
                            const float* __restrict__ fc_b)
{
    const int tid = threadIdx.x;
    if (tid < NH) {
        const int j = tid;
        gScratch.wrz_x[j] = pack2(0.5f * w_ih[j], 0.5f * w_ih[NH + j]);
        gScratch.brz2[j]  = pack2(0.5f * (b_ih[j] + b_hh[j]),
                                  0.5f * (b_ih[NH + j] + b_hh[NH + j]));
        #pragma unroll
        for (int k = 0; k < NH; k++)
            gScratch.wrz_h[j][k] = pack2(0.5f * w_hh[j * NH + k],
                                         0.5f * w_hh[(NH + j) * NH + k]);
        gScratch.wn_h4[j] = w_hh[(2 * NH + 4) * NH + j];
    }
    if (tid >= NH && tid < NH + 2) {
        const int p = tid - NH;
        gScratch.bn2[p]  = pack2(b_hh[2 * NH + 2 * p], b_hh[2 * NH + 2 * p + 1]);
        gScratch.win2[p] = pack2(w_ih[2 * NH + 2 * p], w_ih[2 * NH + 2 * p + 1]);
        gScratch.bin2[p] = pack2(b_ih[2 * NH + 2 * p], b_ih[2 * NH + 2 * p + 1]);
        #pragma unroll
        for (int k = 0; k < NH; k++)
            gScratch.wn_h2[p][k] = pack2(w_hh[(2 * NH + 2 * p) * NH + k],
                                         w_hh[(2 * NH + 2 * p + 1) * NH + k]);
    }
    if (tid >= 8 && tid < 8 + NO) {
        const int o = tid - 8;
        #pragma unroll
        for (int k = 0; k < NH; k++) gScratch.fcw[o][k] = fc_w[o * NH + k];
        gScratch.fcb[o] = fc_b[o];
    }
    if (tid == 12) {
        gScratch.bn4  = b_hh[2 * NH + 4];
        gScratch.win4 = w_ih[2 * NH + 4];
        gScratch.bin4 = b_ih[2 * NH + 4];
    }
}

__global__ __launch_bounds__(THREADS)
void gru_fused_kernel(const float* __restrict__ x, float* __restrict__ out)
{
    const int n = blockIdx.x * THREADS + threadIdx.x;
    if (n >= NSEQ) return;
    const int b = n / NS;
    const int s = n - b * NS;

    const ull NEG1_2 = pack2(-1.0f, -1.0f);
    const ull HALF2  = pack2(0.5f, 0.5f);

    // ---- GRU recurrence, fully unrolled; weights read from __constant__ -----
    float h[NH] = {0.f, 0.f, 0.f, 0.f, 0.f};
    ull h01 = pack2(0.f, 0.f), h23 = h01;
    const float* xp = x + (size_t)b * (NT * NS) + s;

    #pragma unroll
    for (int t = 0; t < NT; t++) {
        const float xv = __ldg(xp + t * NS);
        const ull xv2 = pack2(xv, xv);

        // r/z pre-activations (0.5-scaled): x part
        ull arz[NH];
        #pragma unroll
        for (int j = 0; j < NH; j++) arz[j] = fma2(xv2, cW.wrz_x[j], cW.brz2[j]);

        // n-gate hidden part
        ull an2[2] = {cW.bn2[0], cW.bn2[1]};
        float ah4 = cW.bn4;

        if (t > 0) {  // h == 0 at t == 0: skip the entire h-matvec
            ull hb[NH];
            #pragma unroll
            for (int k = 0; k < NH; k++) hb[k] = pack2(h[k], h[k]);
            #pragma unroll
            for (int k = 0; k < NH; k++) {
                #pragma unroll
                for (int j = 0; j < NH; j++)
                    arz[j] = fma2(cW.wrz_h[j][k], hb[k], arz[j]);
                an2[0] = fma2(cW.wn_h2[0][k], hb[k], an2[0]);
                an2[1] = fma2(cW.wn_h2[1][k], hb[k], an2[1]);
                ah4 = fmaf(cW.wn_h4[k], h[k], ah4);
            }
        }
        float ah[NH];
        unpack2(an2[0], ah[0], ah[1]);
        unpack2(an2[1], ah[2], ah[3]);
        ah[4] = ah4;

        // n-gate x-projection, packed across j pairs
        float ai[NH];
        {
            ull ai01 = fma2(xv2, cW.win2[0], cW.bin2[0]);
            ull ai23 = fma2(xv2, cW.win2[1], cW.bin2[1]);
            unpack2(ai01, ai[0], ai[1]);
            unpack2(ai23, ai[2], ai[3]);
            ai[4] = fmaf(xv, cW.win4, cW.bin4);
        }

        // gate epilogue: sigmoid via 0.5*tanh(0.5x)+0.5, r/z pair-packed
        float z[NH], nn[NH];
        #pragma unroll
        for (int j = 0; j < NH; j++) {
            float ar, az;
            unpack2(arz[j], ar, az);
            ull t2 = pack2(tanh_mufu(ar), tanh_mufu(az));
            ull rz = fma2(HALF2, t2, HALF2);
            float r;
            unpack2(rz, r, z[j]);
            nn[j] = tanh_mufu(fmaf(r, ah[j], ai[j]));
        }

        // h update (1-z)*n + z*h = z*(h-n) + n, j-pair packed
        {
            ull nn01 = pack2(nn[0], nn[1]);
            ull nn23 = pack2(nn[2], nn[3]);
            ull z01  = pack2(z[0], z[1]);
            ull z23  = pack2(z[2], z[3]);
            h01 = fma2(z01, fma2(nn01, NEG1_2, h01), nn01);
            h23 = fma2(z23, fma2(nn23, NEG1_2, h23), nn23);
            h[4] = fmaf(z[4], h[4] - nn[4], nn[4]);
            unpack2(h01, h[0], h[1]);
            unpack2(h23, h[2], h[3]);
        }
    }

    // ---- FC(5 -> 3), strided write out[b][o][s] -----------------------------
    #pragma unroll
    for (int o = 0; o < NO; o++) {
        float y = cW.fcb[o];
        #pragma unroll
        for (int k = 0; k < NH; k++) y = fmaf(cW.fcw[o][k], h[k], y);
        out[((size_t)b * NO + o) * NS + s] = y;
    }
}

extern "C" void kernel_launch(void* const* d_in, const int* in_sizes, int n_in,
                              void* d_out, int out_size)
{
    const float* x    = (const float*)d_in[0];
    const float* w_ih = (const float*)d_in[1];
    const float* w_hh = (const float*)d_in[2];
    const float* b_ih = (const float*)d_in[3];
    const float* b_hh = (const float*)d_in[4];
    const float* fc_w = (const float*)d_in[5];
    const float* fc_b = (const float*)d_in[6];
    float* out = (float*)d_out;

    // 1) pack weights on device, 2) copy into __constant__, 3) main kernel.
    // All async on the capture stream; no allocations.
    prep_kernel<<<1, 32>>>(w_ih, w_hh, b_ih, b_hh, fc_w, fc_b);
    void* scratch_ptr = nullptr;
    cudaGetSymbolAddress(&scratch_ptr, gScratch);
    cudaMemcpyToSymbolAsync(cW, scratch_ptr, sizeof(CW), 0,
                            cudaMemcpyDeviceToDevice, 0);

    const int grid = (NSEQ + THREADS - 1) / THREADS;
    gru_fused_kernel<<<grid, THREADS>>>(x, out);
}